// round 15
// baseline (speedup 1.0000x reference)
#include <cuda_runtime.h>
#include <cuda_fp16.h>
#include <cstdint>

// Problem constants
#define Bx 2
#define Tx 2048
#define Cx 1024
#define Hx 16
#define HDx 64
#define Mx (Bx*Tx)          // 4096
#define N_QKV (3*Cx)        // 3072

// fp16 scratch (device globals: allocation-free per harness rules)
__device__ __half g_xh[(size_t)Mx*Cx];
__device__ __half g_wat[(size_t)N_QKV*Cx];    // W_attn^T [3072][1024]
__device__ __half g_wpt[(size_t)Cx*Cx];       // W_proj^T [1024][1024]
__device__ __half g_qh[(size_t)Bx*Hx*Tx*HDx]; // pre-scaled by 0.125
__device__ __half g_kh[(size_t)Bx*Hx*Tx*HDx];
__device__ __half g_vh[(size_t)Bx*Hx*Tx*HDx];
__device__ __half g_attoh[(size_t)Bx*Tx*Cx];

// ---------------------------------------------------------------------------
// helpers
// ---------------------------------------------------------------------------
__device__ __forceinline__ unsigned smem_u32(const void* p) {
    return (unsigned)__cvta_generic_to_shared(p);
}

__device__ __forceinline__ void mma16(float* c, const unsigned* a, const unsigned* b) {
    asm volatile(
        "mma.sync.aligned.m16n8k16.row.col.f32.f16.f16.f32 "
        "{%0,%1,%2,%3},{%4,%5,%6,%7},{%8,%9},{%0,%1,%2,%3};\n"
        : "+f"(c[0]), "+f"(c[1]), "+f"(c[2]), "+f"(c[3])
        : "r"(a[0]), "r"(a[1]), "r"(a[2]), "r"(a[3]), "r"(b[0]), "r"(b[1]));
}

__device__ __forceinline__ void ldsm4(unsigned& r0, unsigned& r1, unsigned& r2,
                                      unsigned& r3, const __half* p) {
    unsigned a = smem_u32(p);
    asm volatile("ldmatrix.sync.aligned.m8n8.x4.shared.b16 {%0,%1,%2,%3},[%4];\n"
                 : "=r"(r0), "=r"(r1), "=r"(r2), "=r"(r3) : "r"(a));
}

__device__ __forceinline__ void ldsm4t(unsigned& r0, unsigned& r1, unsigned& r2,
                                       unsigned& r3, const __half* p) {
    unsigned a = smem_u32(p);
    asm volatile("ldmatrix.sync.aligned.m8n8.x4.trans.shared.b16 {%0,%1,%2,%3},[%4];\n"
                 : "=r"(r0), "=r"(r1), "=r"(r2), "=r"(r3) : "r"(a));
}

__device__ __forceinline__ void cpa16(const __half* gptr, const __half* sptr) {
    unsigned d = smem_u32(sptr);
    asm volatile("cp.async.cg.shared.global [%0], [%1], 16;\n" :: "r"(d), "l"(gptr));
}
#define CPA_COMMIT() asm volatile("cp.async.commit_group;\n")
#define CPA_WAIT1()  asm volatile("cp.async.wait_group 1;\n" ::: "memory")
#define CPA_WAIT2()  asm volatile("cp.async.wait_group 2;\n" ::: "memory")

__device__ __forceinline__ unsigned h2u(__half2 h) { return *(unsigned*)&h; }

// ---------------------------------------------------------------------------
// pre-pass kernels
// ---------------------------------------------------------------------------
__global__ __launch_bounds__(256) void convert_x_kernel(const float* __restrict__ x)
{
    int i = blockIdx.x * blockDim.x + threadIdx.x;    // over float4
    float4 v = *(const float4*)&x[(size_t)i * 4];
    *(__half2*)&g_xh[(size_t)i * 4]     = __floats2half2_rn(v.x, v.y);
    *(__half2*)&g_xh[(size_t)i * 4 + 2] = __floats2half2_rn(v.z, v.w);
}

// W[K=Cx][N] fp32 -> Wt[N][Cx] fp16 (tiled transpose).
// Destination selected IN DEVICE CODE (never pass __device__ globals as args!)
template <bool ATT>
__global__ __launch_bounds__(256) void transpose_h_kernel(
    const float* __restrict__ W, int N)
{
    __half* Wt = ATT ? g_wat : g_wpt;
    __shared__ __half t[32][33];
    int tx = threadIdx.x, ty = threadIdx.y;
    int n0 = blockIdx.x * 32, k0 = blockIdx.y * 32;
#pragma unroll
    for (int i = 0; i < 32; i += 8)
        t[ty + i][tx] = __float2half_rn(W[(size_t)(k0 + ty + i) * N + n0 + tx]);
    __syncthreads();
#pragma unroll
    for (int i = 0; i < 32; i += 8)
        Wt[(size_t)(n0 + ty + i) * Cx + k0 + tx] = t[tx][ty + i];
}

// ---------------------------------------------------------------------------
// fp16 tensor-core GEMM: out[M,NN] = A[M,K] @ Bt[NN,K]^T + bias.
// Block 128x256, k-chunk 32, 8 warps (2m x 4n), warp tile 64x64.
// 4-stage cp.async ring, 1 barrier per chunk. B pre-transposed [N][K].
// B ldsm lane map: matrix idx lane>>3 -> 0:(n+0,k+0) 1:(n+0,k+8)
//                                       2:(n+8,k+0) 3:(n+8,k+8)
// ---------------------------------------------------------------------------
#define KCH 32
#define LDA 40       // 32 + 8 pad (halves)
#define LDBT 40
#define ASTG (128*LDA)    // 5120 halves
#define BSTG (256*LDBT)   // 10240 halves
#define STAGES 4
#define GEMM_SMEM (STAGES*(ASTG+BSTG)*2)   // 122880 B

template <int NN, bool QKV>
__global__ __launch_bounds__(256) void gemm_h_kernel(
    const float* __restrict__ bias, float* __restrict__ Y,
    float* __restrict__ kout, float* __restrict__ vout)
{
    const int K = Cx;
    const __half* A  = QKV ? g_xh  : g_attoh;
    const __half* Bt = QKV ? g_wat : g_wpt;

    extern __shared__ __half sh[];
    __half* As = sh;                       // [STAGES][128][LDA]
    __half* Bs = sh + STAGES * ASTG;       // [STAGES][256][LDBT]

    int tid = threadIdx.x, lane = tid & 31, w = tid >> 5;
    int wm = w >> 2, wn = w & 3;
    int row0 = blockIdx.y * 128, col0 = blockIdx.x * 256;

    auto issue = [&](int c) {
        int slot = c & 3;
        const __half* gA = A + (size_t)row0 * K + c * KCH;
#pragma unroll
        for (int i = 0; i < 2; i++) {
            int idx = i * 256 + tid;            // 0..511
            int r = idx >> 2, o = (idx & 3) * 8;
            cpa16(gA + (size_t)r * K + o, &As[slot * ASTG + r * LDA + o]);
        }
        const __half* gB = Bt + (size_t)col0 * K + c * KCH;
#pragma unroll
        for (int i = 0; i < 4; i++) {
            int idx = i * 256 + tid;            // 0..1023
            int r = idx >> 2, o = (idx & 3) * 8;
            cpa16(gB + (size_t)r * K + o, &Bs[slot * BSTG + r * LDBT + o]);
        }
    };

    float acc[4][8][4];
#pragma unroll
    for (int mt = 0; mt < 4; mt++)
#pragma unroll
        for (int nt = 0; nt < 8; nt++)
#pragma unroll
            for (int e = 0; e < 4; e++) acc[mt][nt][e] = 0.f;

    issue(0); CPA_COMMIT();
    issue(1); CPA_COMMIT();
    issue(2); CPA_COMMIT();

    int arow = wm * 64 + (lane & 15);
    int acol = (lane >> 4) * 8;
    int bn = wn * 64 + (lane & 7) + ((lane >> 4) & 1) * 8;  // n row
    int bk = ((lane >> 3) & 1) * 8;                          // k offset

    const int NS = K / KCH;   // 32
    for (int s = 0; s < NS; s++) {
        CPA_WAIT2();
        __syncthreads();
        if (s + 3 < NS) issue(s + 3);
        CPA_COMMIT();

        int slot = s & 3;
        const __half* Ab = &As[slot * ASTG];
        const __half* Bb = &Bs[slot * BSTG];
#pragma unroll
        for (int ks = 0; ks < 2; ks++) {
            unsigned af[4][4], bf[4][4];
#pragma unroll
            for (int mt = 0; mt < 4; mt++)
                ldsm4(af[mt][0], af[mt][1], af[mt][2], af[mt][3],
                      &Ab[(arow + mt * 16) * LDA + ks * 16 + acol]);
#pragma unroll
            for (int g = 0; g < 4; g++)
                ldsm4(bf[g][0], bf[g][1], bf[g][2], bf[g][3],
                      &Bb[(bn + g * 16) * LDBT + ks * 16 + bk]);
#pragma unroll
            for (int mt = 0; mt < 4; mt++)
#pragma unroll
                for (int nt = 0; nt < 8; nt++)
                    mma16(acc[mt][nt], af[mt], &bf[nt >> 1][(nt & 1) * 2]);
        }
    }

    // Epilogue
#pragma unroll
    for (int mt = 0; mt < 4; mt++) {
#pragma unroll
        for (int e2 = 0; e2 < 2; e2++) {
            int r = row0 + wm * 64 + mt * 16 + (lane >> 2) + e2 * 8;
            int bb = r >> 11, t = r & 2047;
#pragma unroll
            for (int nt = 0; nt < 8; nt++) {
                int c = col0 + wn * 64 + nt * 8 + (lane & 3) * 2;
                float v0 = acc[mt][nt][e2 * 2 + 0] + bias[c];
                float v1 = acc[mt][nt][e2 * 2 + 1] + bias[c + 1];
                if (QKV) {
                    int sec = c >> 10, within = c & 1023;
                    int h = within >> 6, d = within & 63;
                    size_t idx = ((((size_t)bb * Hx + h) * Tx) + t) * HDx + d;
                    if (sec == 0) {
                        *(__half2*)&g_qh[idx] = __floats2half2_rn(v0 * 0.125f, v1 * 0.125f);
                    } else if (sec == 1) {
                        *(float2*)&kout[idx] = make_float2(v0, v1);
                        *(__half2*)&g_kh[idx] = __floats2half2_rn(v0, v1);
                    } else {
                        *(float2*)&vout[idx] = make_float2(v0, v1);
                        *(__half2*)&g_vh[idx] = __floats2half2_rn(v0, v1);
                    }
                } else {
                    *(float2*)&Y[(size_t)r * NN + c] = make_float2(v0, v1);
                }
            }
        }
    }
}

// ---------------------------------------------------------------------------
// Register-resident flash attention (FA2), causal. 3-stage KV ring. (r11)
// ---------------------------------------------------------------------------
#define ALD 72
#define KVSTG (64*ALD)
#define ATTN_SMEM ((128*ALD + 3*KVSTG + 3*KVSTG) * 2)   // 73728 B

__global__ __launch_bounds__(256, 2) void attn_h_kernel()
{
    extern __shared__ char smc[];
    __half* Qh = (__half*)smc;                 // [128][ALD]
    __half* Kh = Qh + 128 * ALD;               // [3][64][ALD]
    __half* Vh = Kh + 3 * KVSTG;               // [3][64][ALD]

    int tid = threadIdx.x, lane = tid & 31, w = tid >> 5;
    int qt = blockIdx.x, bh = blockIdx.y;
    int g = lane >> 2, t4 = lane & 3;

    const __half* Qg = g_qh + ((size_t)bh * Tx + (size_t)qt * 128) * HDx;
    const __half* Kb0 = g_kh + (size_t)bh * Tx * HDx;
    const __half* Vb0 = g_vh + (size_t)bh * Tx * HDx;

    const int jend = 2 * qt + 2;

    auto issue_kv = [&](int j) {
        int slot = j % 3;
        const __half* Kg = Kb0 + (size_t)j * 64 * HDx;
        const __half* Vg = Vb0 + (size_t)j * 64 * HDx;
#pragma unroll
        for (int i = 0; i < 2; i++) {
            int c = i * 256 + tid;
            int r = c >> 3, o = (c & 7) * 8;
            cpa16(Kg + (size_t)r * HDx + o, &Kh[slot * KVSTG + r * ALD + o]);
            cpa16(Vg + (size_t)r * HDx + o, &Vh[slot * KVSTG + r * ALD + o]);
        }
    };

#pragma unroll
    for (int i = 0; i < 4; i++) {
        int c = i * 256 + tid;
        int r = c >> 3, o = (c & 7) * 8;
        cpa16(Qg + (size_t)r * HDx + o, &Qh[r * ALD + o]);
    }
    issue_kv(0); CPA_COMMIT();
    if (jend > 1) issue_kv(1);
    CPA_COMMIT();

    CPA_WAIT1();
    __syncthreads();

    unsigned qf[4][4];
    {
        int arow = w * 16 + (lane & 15);
        int acol = (lane >> 4) * 8;
#pragma unroll
        for (int ks = 0; ks < 4; ks++)
            ldsm4(qf[ks][0], qf[ks][1], qf[ks][2], qf[ks][3],
                  &Qh[arow * ALD + ks * 16 + acol]);
    }

    float o[8][4];
#pragma unroll
    for (int nt = 0; nt < 8; nt++)
#pragma unroll
        for (int e = 0; e < 4; e++) o[nt][e] = 0.f;
    float m0 = -1e30f, m1 = -1e30f, l0 = 0.f, l1 = 0.f;

    int krow = (lane >> 4) * 8 + (lane & 7);
    int kcol = ((lane >> 3) & 1) * 8;
    int vrow = lane & 15;
    int vcol = (lane >> 4) * 8;

    int row0g = qt * 128 + w * 16 + g;

    for (int j = 0; j < jend; j++) {
        if (j > 0) { CPA_WAIT1(); __syncthreads(); }
        if (j + 2 < jend) issue_kv(j + 2);
        CPA_COMMIT();

        int slot = j % 3;
        const __half* Kb = &Kh[slot * KVSTG];
        const __half* Vb = &Vh[slot * KVSTG];

        bool active = !(j == 2 * qt + 1 && w < 4);

        if (active) {
            float s[8][4];
#pragma unroll
            for (int nt = 0; nt < 8; nt++)
#pragma unroll
                for (int e = 0; e < 4; e++) s[nt][e] = 0.f;

#pragma unroll
            for (int ks = 0; ks < 4; ks++) {
                unsigned bf[4][4];
#pragma unroll
                for (int gg = 0; gg < 4; gg++)
                    ldsm4(bf[gg][0], bf[gg][1], bf[gg][2], bf[gg][3],
                          &Kb[(gg * 16 + krow) * ALD + ks * 16 + kcol]);
#pragma unroll
                for (int nt = 0; nt < 8; nt++)
                    mma16(s[nt], qf[ks], &bf[nt >> 1][(nt & 1) * 2]);
            }

            if (j >= 2 * qt) {
                int colbase = j * 64 + t4 * 2;
#pragma unroll
                for (int nt = 0; nt < 8; nt++) {
                    int c0 = colbase + nt * 8;
                    if (c0 > row0g)          s[nt][0] = -1e30f;
                    if (c0 + 1 > row0g)      s[nt][1] = -1e30f;
                    if (c0 > row0g + 8)      s[nt][2] = -1e30f;
                    if (c0 + 1 > row0g + 8)  s[nt][3] = -1e30f;
                }
            }

            float mx0 = s[0][0], mx1 = s[0][2];
#pragma unroll
            for (int nt = 0; nt < 8; nt++) {
                mx0 = fmaxf(mx0, fmaxf(s[nt][0], s[nt][1]));
                mx1 = fmaxf(mx1, fmaxf(s[nt][2], s[nt][3]));
            }
            mx0 = fmaxf(mx0, __shfl_xor_sync(0xffffffffu, mx0, 1));
            mx0 = fmaxf(mx0, __shfl_xor_sync(0xffffffffu, mx0, 2));
            mx1 = fmaxf(mx1, __shfl_xor_sync(0xffffffffu, mx1, 1));
            mx1 = fmaxf(mx1, __shfl_xor_sync(0xffffffffu, mx1, 2));

            float mn0 = fmaxf(m0, mx0), mn1 = fmaxf(m1, mx1);
            float al0 = __expf(m0 - mn0), al1 = __expf(m1 - mn1);
            m0 = mn0; m1 = mn1;

            unsigned p0[8], p1[8];
            float rs0 = 0.f, rs1 = 0.f;
#pragma unroll
            for (int nt = 0; nt < 8; nt++) {
                float e0 = __expf(s[nt][0] - mn0);
                float e1 = __expf(s[nt][1] - mn0);
                float e2 = __expf(s[nt][2] - mn1);
                float e3 = __expf(s[nt][3] - mn1);
                rs0 += e0 + e1; rs1 += e2 + e3;
                p0[nt] = h2u(__floats2half2_rn(e0, e1));
                p1[nt] = h2u(__floats2half2_rn(e2, e3));
            }
            rs0 += __shfl_xor_sync(0xffffffffu, rs0, 1);
            rs0 += __shfl_xor_sync(0xffffffffu, rs0, 2);
            rs1 += __shfl_xor_sync(0xffffffffu, rs1, 1);
            rs1 += __shfl_xor_sync(0xffffffffu, rs1, 2);
            l0 = l0 * al0 + rs0;
            l1 = l1 * al1 + rs1;

#pragma unroll
            for (int nt = 0; nt < 8; nt++) {
                o[nt][0] *= al0; o[nt][1] *= al0;
                o[nt][2] *= al1; o[nt][3] *= al1;
            }

#pragma unroll
            for (int ks = 0; ks < 4; ks++) {
                unsigned bf[4][4];
#pragma unroll
                for (int gg = 0; gg < 4; gg++)
                    ldsm4t(bf[gg][0], bf[gg][1], bf[gg][2], bf[gg][3],
                           &Vb[(ks * 16 + vrow) * ALD + gg * 16 + vcol]);
                unsigned aP[4] = {p0[2 * ks], p1[2 * ks], p0[2 * ks + 1], p1[2 * ks + 1]};
#pragma unroll
                for (int nt = 0; nt < 8; nt++)
                    mma16(o[nt], aP, &bf[nt >> 1][(nt & 1) * 2]);
            }
        }
    }

    int bb = bh >> 4, h = bh & 15;
    float inv0 = 1.0f / l0, inv1 = 1.0f / l1;
    int r0 = qt * 128 + w * 16 + g;
#pragma unroll
    for (int nt = 0; nt < 8; nt++) {
        int c = nt * 8 + t4 * 2;
        *(__half2*)&g_attoh[((size_t)bb * Tx + r0) * Cx + h * 64 + c] =
            __floats2half2_rn(o[nt][0] * inv0, o[nt][1] * inv0);
        *(__half2*)&g_attoh[((size_t)bb * Tx + r0 + 8) * Cx + h * 64 + c] =
            __floats2half2_rn(o[nt][2] * inv1, o[nt][3] * inv1);
    }
}

// ---------------------------------------------------------------------------
extern "C" void kernel_launch(void* const* d_in, const int* in_sizes, int n_in,
                              void* d_out, int out_size)
{
    const float* x      = (const float*)d_in[0];
    const float* W_attn = (const float*)d_in[1];
    const float* b_attn = (const float*)d_in[2];
    const float* W_proj = (const float*)d_in[3];
    const float* b_proj = (const float*)d_in[4];

    float* y    = (float*)d_out;
    float* kout = y + (size_t)Bx * Tx * Cx;
    float* vout = kout + (size_t)Bx * Hx * Tx * HDx;

    cudaFuncSetAttribute(gemm_h_kernel<N_QKV, true>,
                         cudaFuncAttributeMaxDynamicSharedMemorySize, GEMM_SMEM);
    cudaFuncSetAttribute(gemm_h_kernel<Cx, false>,
                         cudaFuncAttributeMaxDynamicSharedMemorySize, GEMM_SMEM);
    cudaFuncSetAttribute(attn_h_kernel,
                         cudaFuncAttributeMaxDynamicSharedMemorySize, ATTN_SMEM);

    convert_x_kernel<<<Mx * Cx / 4 / 256, 256>>>(x);
    transpose_h_kernel<true><<<dim3(N_QKV / 32, Cx / 32), dim3(32, 8)>>>(W_attn, N_QKV);
    transpose_h_kernel<false><<<dim3(Cx / 32, Cx / 32), dim3(32, 8)>>>(W_proj, Cx);

    gemm_h_kernel<N_QKV, true><<<dim3(N_QKV / 256, Mx / 128), 256, GEMM_SMEM>>>(
        b_attn, nullptr, kout, vout);
    attn_h_kernel<<<dim3(Tx / 128, Bx * Hx), 256, ATTN_SMEM>>>();
    gemm_h_kernel<Cx, false><<<dim3(Cx / 256, Mx / 128), 256, GEMM_SMEM>>>(
        b_proj, y, nullptr, nullptr);
}

// round 16
// speedup vs baseline: 1.1339x; 1.1339x over previous
#include <cuda_runtime.h>
#include <cuda_fp16.h>
#include <cstdint>

// Problem constants
#define Bx 2
#define Tx 2048
#define Cx 1024
#define Hx 16
#define HDx 64
#define Mx (Bx*Tx)          // 4096
#define N_QKV (3*Cx)        // 3072

// fp16 scratch (device globals: allocation-free per harness rules)
__device__ __half g_xh[(size_t)Mx*Cx];
__device__ __half g_wah[(size_t)Cx*N_QKV];
__device__ __half g_wph[(size_t)Cx*Cx];
__device__ __half g_qh[(size_t)Bx*Hx*Tx*HDx];    // pre-scaled by 0.125
__device__ __half g_kh[(size_t)Bx*Hx*Tx*HDx];
__device__ __half g_vh[(size_t)Bx*Hx*Tx*HDx];
__device__ __half g_attoh[(size_t)Bx*Tx*Cx];

// ---------------------------------------------------------------------------
// helpers
// ---------------------------------------------------------------------------
__device__ __forceinline__ unsigned smem_u32(const void* p) {
    return (unsigned)__cvta_generic_to_shared(p);
}

__device__ __forceinline__ void mma16(float* c, const unsigned* a, const unsigned* b) {
    asm volatile(
        "mma.sync.aligned.m16n8k16.row.col.f32.f16.f16.f32 "
        "{%0,%1,%2,%3},{%4,%5,%6,%7},{%8,%9},{%0,%1,%2,%3};\n"
        : "+f"(c[0]), "+f"(c[1]), "+f"(c[2]), "+f"(c[3])
        : "r"(a[0]), "r"(a[1]), "r"(a[2]), "r"(a[3]), "r"(b[0]), "r"(b[1]));
}

__device__ __forceinline__ void ldsm4(unsigned& r0, unsigned& r1, unsigned& r2,
                                      unsigned& r3, const __half* p) {
    unsigned a = smem_u32(p);
    asm volatile("ldmatrix.sync.aligned.m8n8.x4.shared.b16 {%0,%1,%2,%3},[%4];\n"
                 : "=r"(r0), "=r"(r1), "=r"(r2), "=r"(r3) : "r"(a));
}

__device__ __forceinline__ void ldsm4t(unsigned& r0, unsigned& r1, unsigned& r2,
                                       unsigned& r3, const __half* p) {
    unsigned a = smem_u32(p);
    asm volatile("ldmatrix.sync.aligned.m8n8.x4.trans.shared.b16 {%0,%1,%2,%3},[%4];\n"
                 : "=r"(r0), "=r"(r1), "=r"(r2), "=r"(r3) : "r"(a));
}

__device__ __forceinline__ void cpa16(const __half* gptr, const __half* sptr) {
    unsigned d = smem_u32(sptr);
    asm volatile("cp.async.cg.shared.global [%0], [%1], 16;\n" :: "r"(d), "l"(gptr));
}
#define CPA_COMMIT() asm volatile("cp.async.commit_group;\n")
#define CPA_WAIT1()  asm volatile("cp.async.wait_group 1;\n" ::: "memory")
#define CPA_WAIT3()  asm volatile("cp.async.wait_group 3;\n" ::: "memory")

__device__ __forceinline__ unsigned h2u(__half2 h) { return *(unsigned*)&h; }

// ---------------------------------------------------------------------------
// fp32 -> fp16 conversion pre-pass (x, W_attn, W_proj)
// ---------------------------------------------------------------------------
__global__ __launch_bounds__(256) void convert_inputs_kernel(
    const float* __restrict__ x, const float* __restrict__ wa,
    const float* __restrict__ wp)
{
    const int X4 = Mx * Cx / 4, WA4 = Cx * N_QKV / 4, WP4 = Cx * Cx / 4;
    int i = blockIdx.x * blockDim.x + threadIdx.x;
    const float* src; __half* dst; int off;
    if (i < X4)                 { src = x;  dst = g_xh;  off = i; }
    else if (i < X4 + WA4)      { src = wa; dst = g_wah; off = i - X4; }
    else if (i < X4 + WA4 + WP4){ src = wp; dst = g_wph; off = i - X4 - WA4; }
    else return;
    float4 v = *(const float4*)&src[(size_t)off * 4];
    *(__half2*)&dst[(size_t)off * 4]     = __floats2half2_rn(v.x, v.y);
    *(__half2*)&dst[(size_t)off * 4 + 2] = __floats2half2_rn(v.z, v.w);
}

// ---------------------------------------------------------------------------
// fp16 tensor-core GEMM, 5-stage cp.async ring, 1 barrier per k-chunk.
// Block 128x128, k-chunk 32, 8 warps (2m x 4n), warp tile 64x32, m16n8k16.
// ---------------------------------------------------------------------------
#define KCH 32
#define LDA 40      // 32 + 8 pad (halves)
#define LDB 136     // 128 + 8 pad (halves)
#define ASTG (128*LDA)   // 5120 halves
#define BSTG (KCH*LDB)   // 4352 halves
#define STAGES 5
#define GEMM_SMEM (STAGES*(ASTG+BSTG)*2)   // 94720 B

template <int NN, bool QKV>
__global__ __launch_bounds__(256, 2) void gemm_h_kernel(
    const float* __restrict__ bias, float* __restrict__ Y,
    float* __restrict__ kout, float* __restrict__ vout)
{
    const int K = Cx;
    const __half* A = QKV ? g_xh : g_attoh;
    const __half* W = QKV ? g_wah : g_wph;

    extern __shared__ __half sh[];
    __half* As = sh;                       // [STAGES][128][LDA]
    __half* Bs = sh + STAGES * ASTG;       // [STAGES][KCH][LDB]

    int tid = threadIdx.x, lane = tid & 31, w = tid >> 5;
    int wm = w >> 2, wn = w & 3;
    int row0 = blockIdx.y * 128, col0 = blockIdx.x * 128;

    auto issue = [&](int s) {
        int slot = s % STAGES;
        const __half* gA = A + (size_t)row0 * K + s * KCH;
#pragma unroll
        for (int i = 0; i < 2; i++) {
            int c = i * 256 + tid;              // 0..511
            int r = c >> 2, o = (c & 3) * 8;
            cpa16(gA + (size_t)r * K + o, &As[slot * ASTG + r * LDA + o]);
        }
        const __half* gB = W + (size_t)(s * KCH) * NN + col0;
#pragma unroll
        for (int i = 0; i < 2; i++) {
            int c = i * 256 + tid;
            int r = c >> 4, o = (c & 15) * 8;
            cpa16(gB + (size_t)r * NN + o, &Bs[slot * BSTG + r * LDB + o]);
        }
    };

    float acc[4][4][4];
#pragma unroll
    for (int mt = 0; mt < 4; mt++)
#pragma unroll
        for (int nt = 0; nt < 4; nt++)
#pragma unroll
            for (int e = 0; e < 4; e++) acc[mt][nt][e] = 0.f;

    issue(0); CPA_COMMIT();
    issue(1); CPA_COMMIT();
    issue(2); CPA_COMMIT();
    issue(3); CPA_COMMIT();

    int arow = wm * 64 + (lane & 15);
    int acol = (lane >> 4) * 8;
    int brow = lane & 15;
    int bcol = wn * 32 + (lane >> 4) * 8;

    const int NS = K / KCH;   // 32
    for (int s = 0; s < NS; s++) {
        CPA_WAIT3();
        __syncthreads();                   // stage s ready; slot (s-1)%5 free
        if (s + 4 < NS) issue(s + 4);      // into slot (s+4)%5 == (s-1)%5
        CPA_COMMIT();                      // unconditional: keeps group count exact

        int slot = s % STAGES;
        const __half* Ab = &As[slot * ASTG];
        const __half* Bb = &Bs[slot * BSTG];
#pragma unroll
        for (int ks = 0; ks < 2; ks++) {
            unsigned af[4][4], bf[2][4];
#pragma unroll
            for (int mt = 0; mt < 4; mt++)
                ldsm4(af[mt][0], af[mt][1], af[mt][2], af[mt][3],
                      &Ab[(arow + mt * 16) * LDA + ks * 16 + acol]);
#pragma unroll
            for (int g = 0; g < 2; g++)
                ldsm4t(bf[g][0], bf[g][1], bf[g][2], bf[g][3],
                       &Bb[(ks * 16 + brow) * LDB + bcol + g * 16]);
#pragma unroll
            for (int mt = 0; mt < 4; mt++)
#pragma unroll
                for (int nt = 0; nt < 4; nt++)
                    mma16(acc[mt][nt], af[mt], &bf[nt >> 1][(nt & 1) * 2]);
        }
    }

    // Epilogue
#pragma unroll
    for (int mt = 0; mt < 4; mt++) {
#pragma unroll
        for (int e2 = 0; e2 < 2; e2++) {
            int r = row0 + wm * 64 + mt * 16 + (lane >> 2) + e2 * 8;
#pragma unroll
            for (int nt = 0; nt < 4; nt++) {
                int c = col0 + wn * 32 + nt * 8 + (lane & 3) * 2;
                float v0 = acc[mt][nt][e2 * 2 + 0] + bias[c];
                float v1 = acc[mt][nt][e2 * 2 + 1] + bias[c + 1];
                if (QKV) {
                    int bb = r >> 11, t = r & 2047;
                    int sec = c >> 10, within = c & 1023;
                    int h = within >> 6, d = within & 63;
                    size_t idx = ((((size_t)bb * Hx + h) * Tx) + t) * HDx + d;
                    if (sec == 0) {
                        *(__half2*)&g_qh[idx] = __floats2half2_rn(v0 * 0.125f, v1 * 0.125f);
                    } else if (sec == 1) {
                        *(float2*)&kout[idx] = make_float2(v0, v1);
                        *(__half2*)&g_kh[idx] = __floats2half2_rn(v0, v1);
                    } else {
                        *(float2*)&vout[idx] = make_float2(v0, v1);
                        *(__half2*)&g_vh[idx] = __floats2half2_rn(v0, v1);
                    }
                } else {
                    *(float2*)&Y[(size_t)r * NN + c] = make_float2(v0, v1);
                }
            }
        }
    }
}

// ---------------------------------------------------------------------------
// Register-resident flash attention (FA2), causal. 3-stage KV ring,
// one barrier per tile. LPT scheduling: big q-tiles launch first.
// ---------------------------------------------------------------------------
#define ALD 72
#define KVSTG (64*ALD)
#define ATTN_SMEM ((128*ALD + 3*KVSTG + 3*KVSTG) * 2)   // 73728 B

__global__ __launch_bounds__(256, 2) void attn_h_kernel()
{
    extern __shared__ char smc[];
    __half* Qh = (__half*)smc;                 // [128][ALD]
    __half* Kh = Qh + 128 * ALD;               // [3][64][ALD]
    __half* Vh = Kh + 3 * KVSTG;               // [3][64][ALD]

    int tid = threadIdx.x, lane = tid & 31, w = tid >> 5;
    int qt = (int)gridDim.x - 1 - (int)blockIdx.x;   // LPT: longest first
    int bh = blockIdx.y;
    int g = lane >> 2, t4 = lane & 3;

    const __half* Qg = g_qh + ((size_t)bh * Tx + (size_t)qt * 128) * HDx;
    const __half* Kb0 = g_kh + (size_t)bh * Tx * HDx;
    const __half* Vb0 = g_vh + (size_t)bh * Tx * HDx;

    const int jend = 2 * qt + 2;

    auto issue_kv = [&](int j) {
        int slot = j % 3;
        const __half* Kg = Kb0 + (size_t)j * 64 * HDx;
        const __half* Vg = Vb0 + (size_t)j * 64 * HDx;
#pragma unroll
        for (int i = 0; i < 2; i++) {
            int c = i * 256 + tid;
            int r = c >> 3, o = (c & 7) * 8;
            cpa16(Kg + (size_t)r * HDx + o, &Kh[slot * KVSTG + r * ALD + o]);
            cpa16(Vg + (size_t)r * HDx + o, &Vh[slot * KVSTG + r * ALD + o]);
        }
    };

#pragma unroll
    for (int i = 0; i < 4; i++) {
        int c = i * 256 + tid;
        int r = c >> 3, o = (c & 7) * 8;
        cpa16(Qg + (size_t)r * HDx + o, &Qh[r * ALD + o]);
    }
    issue_kv(0); CPA_COMMIT();
    if (jend > 1) issue_kv(1);
    CPA_COMMIT();

    CPA_WAIT1();
    __syncthreads();                    // Q + KV0 ready

    unsigned qf[4][4];
    {
        int arow = w * 16 + (lane & 15);
        int acol = (lane >> 4) * 8;
#pragma unroll
        for (int ks = 0; ks < 4; ks++)
            ldsm4(qf[ks][0], qf[ks][1], qf[ks][2], qf[ks][3],
                  &Qh[arow * ALD + ks * 16 + acol]);
    }

    float o[8][4];
#pragma unroll
    for (int nt = 0; nt < 8; nt++)
#pragma unroll
        for (int e = 0; e < 4; e++) o[nt][e] = 0.f;
    float m0 = -1e30f, m1 = -1e30f, l0 = 0.f, l1 = 0.f;

    int krow = (lane >> 4) * 8 + (lane & 7);
    int kcol = ((lane >> 3) & 1) * 8;
    int vrow = lane & 15;
    int vcol = (lane >> 4) * 8;

    int row0g = qt * 128 + w * 16 + g;

    for (int j = 0; j < jend; j++) {
        if (j > 0) { CPA_WAIT1(); __syncthreads(); }
        if (j + 2 < jend) issue_kv(j + 2);
        CPA_COMMIT();

        int slot = j % 3;
        const __half* Kb = &Kh[slot * KVSTG];
        const __half* Vb = &Vh[slot * KVSTG];

        bool active = !(j == 2 * qt + 1 && w < 4);

        if (active) {
            float s[8][4];
#pragma unroll
            for (int nt = 0; nt < 8; nt++)
#pragma unroll
                for (int e = 0; e < 4; e++) s[nt][e] = 0.f;

#pragma unroll
            for (int ks = 0; ks < 4; ks++) {
                unsigned bf[4][4];
#pragma unroll
                for (int gg = 0; gg < 4; gg++)
                    ldsm4(bf[gg][0], bf[gg][1], bf[gg][2], bf[gg][3],
                          &Kb[(gg * 16 + krow) * ALD + ks * 16 + kcol]);
#pragma unroll
                for (int nt = 0; nt < 8; nt++)
                    mma16(s[nt], qf[ks], &bf[nt >> 1][(nt & 1) * 2]);
            }

            if (j >= 2 * qt) {
                int colbase = j * 64 + t4 * 2;
#pragma unroll
                for (int nt = 0; nt < 8; nt++) {
                    int c0 = colbase + nt * 8;
                    if (c0 > row0g)          s[nt][0] = -1e30f;
                    if (c0 + 1 > row0g)      s[nt][1] = -1e30f;
                    if (c0 > row0g + 8)      s[nt][2] = -1e30f;
                    if (c0 + 1 > row0g + 8)  s[nt][3] = -1e30f;
                }
            }

            float mx0 = s[0][0], mx1 = s[0][2];
#pragma unroll
            for (int nt = 0; nt < 8; nt++) {
                mx0 = fmaxf(mx0, fmaxf(s[nt][0], s[nt][1]));
                mx1 = fmaxf(mx1, fmaxf(s[nt][2], s[nt][3]));
            }
            mx0 = fmaxf(mx0, __shfl_xor_sync(0xffffffffu, mx0, 1));
            mx0 = fmaxf(mx0, __shfl_xor_sync(0xffffffffu, mx0, 2));
            mx1 = fmaxf(mx1, __shfl_xor_sync(0xffffffffu, mx1, 1));
            mx1 = fmaxf(mx1, __shfl_xor_sync(0xffffffffu, mx1, 2));

            float mn0 = fmaxf(m0, mx0), mn1 = fmaxf(m1, mx1);
            float al0 = __expf(m0 - mn0), al1 = __expf(m1 - mn1);
            m0 = mn0; m1 = mn1;

            unsigned p0[8], p1[8];
            float rs0 = 0.f, rs1 = 0.f;
#pragma unroll
            for (int nt = 0; nt < 8; nt++) {
                float e0 = __expf(s[nt][0] - mn0);
                float e1 = __expf(s[nt][1] - mn0);
                float e2 = __expf(s[nt][2] - mn1);
                float e3 = __expf(s[nt][3] - mn1);
                rs0 += e0 + e1; rs1 += e2 + e3;
                p0[nt] = h2u(__floats2half2_rn(e0, e1));
                p1[nt] = h2u(__floats2half2_rn(e2, e3));
            }
            rs0 += __shfl_xor_sync(0xffffffffu, rs0, 1);
            rs0 += __shfl_xor_sync(0xffffffffu, rs0, 2);
            rs1 += __shfl_xor_sync(0xffffffffu, rs1, 1);
            rs1 += __shfl_xor_sync(0xffffffffu, rs1, 2);
            l0 = l0 * al0 + rs0;
            l1 = l1 * al1 + rs1;

#pragma unroll
            for (int nt = 0; nt < 8; nt++) {
                o[nt][0] *= al0; o[nt][1] *= al0;
                o[nt][2] *= al1; o[nt][3] *= al1;
            }

#pragma unroll
            for (int ks = 0; ks < 4; ks++) {
                unsigned bf[4][4];
#pragma unroll
                for (int gg = 0; gg < 4; gg++)
                    ldsm4t(bf[gg][0], bf[gg][1], bf[gg][2], bf[gg][3],
                           &Vb[(ks * 16 + vrow) * ALD + gg * 16 + vcol]);
                unsigned aP[4] = {p0[2 * ks], p1[2 * ks], p0[2 * ks + 1], p1[2 * ks + 1]};
#pragma unroll
                for (int nt = 0; nt < 8; nt++)
                    mma16(o[nt], aP, &bf[nt >> 1][(nt & 1) * 2]);
            }
        }
    }

    int bb = bh >> 4, h = bh & 15;
    float inv0 = 1.0f / l0, inv1 = 1.0f / l1;
    int r0 = qt * 128 + w * 16 + g;
#pragma unroll
    for (int nt = 0; nt < 8; nt++) {
        int c = nt * 8 + t4 * 2;
        *(__half2*)&g_attoh[((size_t)bb * Tx + r0) * Cx + h * 64 + c] =
            __floats2half2_rn(o[nt][0] * inv0, o[nt][1] * inv0);
        *(__half2*)&g_attoh[((size_t)bb * Tx + r0 + 8) * Cx + h * 64 + c] =
            __floats2half2_rn(o[nt][2] * inv1, o[nt][3] * inv1);
    }
}

// ---------------------------------------------------------------------------
extern "C" void kernel_launch(void* const* d_in, const int* in_sizes, int n_in,
                              void* d_out, int out_size)
{
    const float* x      = (const float*)d_in[0];
    const float* W_attn = (const float*)d_in[1];
    const float* b_attn = (const float*)d_in[2];
    const float* W_proj = (const float*)d_in[3];
    const float* b_proj = (const float*)d_in[4];

    float* y    = (float*)d_out;
    float* kout = y + (size_t)Bx * Tx * Cx;
    float* vout = kout + (size_t)Bx * Hx * Tx * HDx;

    cudaFuncSetAttribute(gemm_h_kernel<N_QKV, true>,
                         cudaFuncAttributeMaxDynamicSharedMemorySize, GEMM_SMEM);
    cudaFuncSetAttribute(gemm_h_kernel<Cx, false>,
                         cudaFuncAttributeMaxDynamicSharedMemorySize, GEMM_SMEM);
    cudaFuncSetAttribute(attn_h_kernel,
                         cudaFuncAttributeMaxDynamicSharedMemorySize, ATTN_SMEM);

    const int TOT4 = (Mx * Cx + Cx * N_QKV + Cx * Cx) / 4;
    convert_inputs_kernel<<<TOT4 / 256, 256>>>(x, W_attn, W_proj);
    gemm_h_kernel<N_QKV, true><<<dim3(N_QKV / 128, Mx / 128), 256, GEMM_SMEM>>>(
        b_attn, nullptr, kout, vout);
    attn_h_kernel<<<dim3(Tx / 128, Bx * Hx), 256, ATTN_SMEM>>>();
    gemm_h_kernel<Cx, false><<<dim3(Cx / 128, Mx / 128), 256, GEMM_SMEM>>>(
        b_proj, y, nullptr, nullptr);
}